// round 8
// baseline (speedup 1.0000x reference)
#include <cuda_runtime.h>

// P1 vector FEM eval on structured 16x16 triangulated unit square.
// Bit-faithful numerics (R4): exact fp32 classification, interior-gridline
// bbox exclusion, argmax tie -> upper triangle, reference op-order output.
//
// Perf (R8): 4 points/thread (2 independent float4 LDG -> MLP=2 on the DRAM
// trip), 128 CTAs x 128 threads = single wave + 4-warp barrier; smem weight
// stage filled with float4 loads (146 LDG.128/block instead of 578 LDG.32),
// interleaved (wx,wy) pairs so each vertex gather is one LDS.64 broadcast.

__device__ __forceinline__ void eval_point(
    float px, float py, const float2* __restrict__ w, float& ox, float& oy)
{
    const float NTOL = -1e-10f;

    float fx = __fmul_rn(px, 16.0f);    // exact
    float fy = __fmul_rn(py, 16.0f);
    int i = (int)floorf(fx);
    int j = (int)floorf(fy);
    i = min(max(i, 0), 15);
    j = min(max(j, 0), 15);

    float u = __fsub_rn(fx, (float)i);  // exact
    float v = __fsub_rn(fy, (float)j);  // exact

    // reference-faithful inside tests (exact fp32)
    float P  = __fsub_rn(fx, fy);                 // fl(16px - 16py)
    float s1 = __fsub_rn(P, (float)(i - j));      // T1 s
    float t2 = -s1;                               // T2 t (bitwise)

    bool in1 = (s1 > NTOL) && (v > NTOL) && (__fadd_rn(s1, v) < 1.0f);
    bool in2 = (u  > NTOL) && (t2 > NTOL) && (__fadd_rn(u, t2) < 1.0f);

    // interior gridline points fail every strict bbox in the reference
    bool on_g = ((u == 0.0f) && (i > 0)) || ((v == 0.0f) && (j > 0));
    bool hit = (px >= 0.0f) && (px < 1.0f) && (py >= 0.0f) && (py < 1.0f) &&
               !on_g && (in1 || in2);

    // branchless triangle select (argmax tie -> T2)
    int v00 = i * 17 + j;
    float s  = in2 ? u : __fsub_rn(u, v);
    float t  = in2 ? __fsub_rn(v, u) : v;
    int  k1  = in2 ? (v00 + 18) : (v00 + 17);
    int  k2  = in2 ? (v00 + 1)  : (v00 + 18);
    float b0 = __fsub_rn(__fsub_rn(1.0f, s), t);

    float2 w0 = w[v00];
    float2 w1 = w[k1];
    float2 w2 = w[k2];

    float rx = __fadd_rn(__fadd_rn(__fmul_rn(b0, w0.x), __fmul_rn(s, w1.x)),
                         __fmul_rn(t, w2.x));
    float ry = __fadd_rn(__fadd_rn(__fmul_rn(b0, w0.y), __fmul_rn(s, w1.y)),
                         __fmul_rn(t, w2.y));
    ox = hit ? rx : 0.0f;
    oy = hit ? ry : 0.0f;
}

__global__ void __launch_bounds__(128)
p1_eval_kernel(const float4* __restrict__ pts4,
               const float*  __restrict__ wx,
               const float*  __restrict__ wy,
               float4* __restrict__ out4)
{
    __shared__ float2 wsh[289];

    int tid = threadIdx.x;
    int gid = blockIdx.x * blockDim.x + tid;
    const int STRIDE = 128 * 128;   // total threads (grid is fixed geometry)

    // issue both (independent) point loads first: MLP=2 on the long trip,
    // overlapping the smem weight fill below
    float4 pa = pts4[gid];            // points 0,1
    float4 pb = pts4[gid + STRIDE];   // points 2,3

    // vectorized weight stage: threads 0..71 each move 4 (wx,wy) pairs,
    // thread 72 handles the 289th element
    if (tid < 72) {
        float4 a = __ldg((const float4*)wx + tid);
        float4 b = __ldg((const float4*)wy + tid);
        int base = tid * 4;
        wsh[base + 0] = make_float2(a.x, b.x);
        wsh[base + 1] = make_float2(a.y, b.y);
        wsh[base + 2] = make_float2(a.z, b.z);
        wsh[base + 3] = make_float2(a.w, b.w);
    } else if (tid == 72) {
        wsh[288] = make_float2(__ldg(wx + 288), __ldg(wy + 288));
    }
    __syncthreads();

    float4 ra, rb;
    eval_point(pa.x, pa.y, wsh, ra.x, ra.y);
    eval_point(pa.z, pa.w, wsh, ra.z, ra.w);
    eval_point(pb.x, pb.y, wsh, rb.x, rb.y);
    eval_point(pb.z, pb.w, wsh, rb.z, rb.w);

    out4[gid]          = ra;
    out4[gid + STRIDE] = rb;
}

extern "C" void kernel_launch(void* const* d_in, const int* in_sizes, int n_in,
                              void* d_out, int out_size)
{
    const float4* pts4 = (const float4*)d_in[0];
    const float*  wx   = (const float*)d_in[1];
    const float*  wy   = (const float*)d_in[2];
    float4* out4 = (float4*)d_out;

    // 65536 points -> 32768 float4 -> 128 CTAs x 128 thr x 2 float4 each
    p1_eval_kernel<<<128, 128>>>(pts4, wx, wy, out4);
}